// round 10
// baseline (speedup 1.0000x reference)
#include <cuda_runtime.h>
#include <cstdint>

// Multi-scale deformable attention, nearest sampling, zero padding.
//   value: (6, 14960, 8, 32) f32   loc: (6, 40000, 8, 4, 4, 2) f32
//   out:   (6, 40000, 256) f32
//
// Block = 4 queries, 256 threads.
// Phase 1: thread t handles 2 consecutive points (same level) of one (q,h):
//          one float4 loc load, shared level constants, one STS.128 of
//          {off0, mask0, off1, mask1}.
// Phase 2: warp = (query, 4 heads); 8 x { LDS.128 -> 2 x (LDG.128 + 4 FFMA) }.
//          Full-warp STG.128 writes 4 heads x 128B.

#define BS        6
#define NQ        40000
#define NHEADS    8
#define NKEYS     14960
#define QPB       4            // queries per block

__global__ __launch_bounds__(256, 8)
void msda_kernel(const float* __restrict__ value,
                 const float* __restrict__ loc,
                 float* __restrict__ out)
{
    // 9 int4 per (qi,h): 8 point-pairs + 1 pad -> 144B row stride,
    // conflict-free for STS.128 scatter and 4-group LDS.128 broadcast.
    __shared__ int4 skey[QPB * NHEADS * 9];

    const int tid = threadIdx.x;
    const int b   = blockIdx.y;
    const int q0  = blockIdx.x * QPB;

    // ---------------- Phase 1: 256 threads x 1 point-pair ----------------
    {
        const int qi = tid >> 6;          // query in block
        const int h  = (tid >> 3) & 7;    // head
        const int pp = tid & 7;           // point pair (points 2pp, 2pp+1)
        const int l  = pp >> 1;           // level (pairs never straddle levels)

        const int W  = 176 >> l;
        const int Hh = 64  >> l;
        // level offsets 0, 11264, 14080, 14784 (geometric /4 partial sums)
        const int base = (45056 - (45056 >> (2 * l))) / 3;

        const unsigned loc4 = ((unsigned)(b * NQ + q0 + qi) * NHEADS + h) * 8 + pp;
        const float4 s = __ldg(reinterpret_cast<const float4*>(loc) + loc4);

        // Replicate reference arithmetic exactly (no fma contraction):
        // g = 2*s - 1 ; x = ((g + 1) * w) * 0.5 - 0.5 ; ix = rint(x)
        const float fW = (float)W, fH = (float)Hh;

        float gx0 = __fadd_rn(__fmul_rn(2.0f, s.x), -1.0f);
        float gy0 = __fadd_rn(__fmul_rn(2.0f, s.y), -1.0f);
        float x0  = __fadd_rn(__fmul_rn(__fmul_rn(__fadd_rn(gx0, 1.0f), fW), 0.5f), -0.5f);
        float y0  = __fadd_rn(__fmul_rn(__fmul_rn(__fadd_rn(gy0, 1.0f), fH), 0.5f), -0.5f);
        const int ix0 = __float2int_rn(x0);
        const int iy0 = __float2int_rn(y0);

        float gx1 = __fadd_rn(__fmul_rn(2.0f, s.z), -1.0f);
        float gy1 = __fadd_rn(__fmul_rn(2.0f, s.w), -1.0f);
        float x1  = __fadd_rn(__fmul_rn(__fmul_rn(__fadd_rn(gx1, 1.0f), fW), 0.5f), -0.5f);
        float y1  = __fadd_rn(__fmul_rn(__fmul_rn(__fadd_rn(gy1, 1.0f), fH), 0.5f), -0.5f);
        const int ix1 = __float2int_rn(x1);
        const int iy1 = __float2int_rn(y1);

        const bool v0 = ((unsigned)ix0 < (unsigned)W) & ((unsigned)iy0 < (unsigned)Hh);
        const bool v1 = ((unsigned)ix1 < (unsigned)W) & ((unsigned)iy1 < (unsigned)Hh);

        const int k0 = base + min(max(iy0, 0), Hh - 1) * W + min(max(ix0, 0), W - 1);
        const int k1 = base + min(max(iy1, 0), Hh - 1) * W + min(max(ix1, 0), W - 1);

        skey[(qi * NHEADS + h) * 9 + pp] =
            make_int4(k0 << 10, __float_as_int(v0 ? 1.0f : 0.0f),
                      k1 << 10, __float_as_int(v1 ? 1.0f : 0.0f));
    }

    __syncthreads();

    // ---------------- Phase 2: gather (warp = one query, 4 heads) ----------
    const int w     = tid >> 5;          // 0..7
    const int lane  = tid & 31;
    const int qi    = w >> 1;
    const int hbase = (w & 1) << 2;
    const int g     = lane >> 3;         // head group within warp
    const int h     = hbase + g;
    const int d4    = lane & 7;          // float4 slot within the 128B line

    // value[b] slice byte offsets all fit in 32 bits (92 MB total)
    const char* vbase = reinterpret_cast<const char*>(value)
                      + (unsigned)b * (NKEYS * NHEADS * 32u * 4u)
                      + (unsigned)((h << 7) + (d4 << 4));
    const int4* kp = &skey[(qi * NHEADS + h) * 9];

    float4 acc = make_float4(0.f, 0.f, 0.f, 0.f);
#pragma unroll
    for (int pp = 0; pp < 8; ++pp) {
        const int4 km = kp[pp];                                  // LDS.128
        const float4 va = __ldg(reinterpret_cast<const float4*>(vbase + km.x));
        const float  ma = __int_as_float(km.y);
        acc.x = __fmaf_rn(va.x, ma, acc.x);
        acc.y = __fmaf_rn(va.y, ma, acc.y);
        acc.z = __fmaf_rn(va.z, ma, acc.z);
        acc.w = __fmaf_rn(va.w, ma, acc.w);

        const float4 vb = __ldg(reinterpret_cast<const float4*>(vbase + km.z));
        const float  mb = __int_as_float(km.w);
        acc.x = __fmaf_rn(vb.x, mb, acc.x);
        acc.y = __fmaf_rn(vb.y, mb, acc.y);
        acc.z = __fmaf_rn(vb.z, mb, acc.z);
        acc.w = __fmaf_rn(vb.w, mb, acc.w);
    }

    // Full-warp 512B store: 4 heads x 128B for this query.
    float4* op4 = reinterpret_cast<float4*>(out)
                + (unsigned)((b * NQ + q0 + qi) * 64 + (hbase << 3) + lane);
    *op4 = acc;
}

extern "C" void kernel_launch(void* const* d_in, const int* in_sizes, int n_in,
                              void* d_out, int out_size)
{
    const float* value = (const float*)d_in[0];
    // d_in[1] = value_spatial_shapes (constants, folded into the kernel)
    const float* loc   = (const float*)d_in[2];
    float* out         = (float*)d_out;

    dim3 grid(NQ / QPB, BS);
    msda_kernel<<<grid, 256>>>(value, loc, out);
}

// round 11
// speedup vs baseline: 1.0953x; 1.0953x over previous
#include <cuda_runtime.h>
#include <cstdint>

// Multi-scale deformable attention, nearest sampling, zero padding.
//   value: (6, 14960, 8, 32) f32   loc: (6, 40000, 8, 4, 4, 2) f32
//   out:   (6, 40000, 256) f32
//
// Block = 4 queries, 256 threads.
// Phase 1 (paired): thread t handles 2 consecutive points (same level) of one
//          (q,h): one float4 loc load, shared level constants, one STS.128 of
//          {off0, mask0, off1, mask1}.
// Phase 2 (R9 mainloop, unchanged): warp = (query, 4 heads); 16 independent
//          iterations of LDS.64 (key+mask broadcast per 8-lane group,
//          conflict-free 144B row stride) + LDG.128 + 4 masked FFMA.
//          Full-warp STG.128 writes 4 heads x 128B.

#define BS        6
#define NQ        40000
#define NHEADS    8
#define NKEYS     14960
#define QPB       4            // queries per block

__global__ __launch_bounds__(256, 8)
void msda_kernel(const float* __restrict__ value,
                 const float* __restrict__ loc,
                 float* __restrict__ out)
{
    // Row per (qi,h): 16 int2 keys + 2 int2 pad = 18 int2 = 144 bytes.
    // 144B stride makes both the phase-1 STS.128 scatter and the phase-2
    // 4-group LDS.64 broadcast bank-conflict-free.
    __shared__ int2 skey[QPB * NHEADS * 18];

    const int tid = threadIdx.x;
    const int b   = blockIdx.y;
    const int q0  = blockIdx.x * QPB;

    // ---------------- Phase 1: 256 threads x 1 point-pair ----------------
    {
        const int qi = tid >> 6;          // query in block
        const int h  = (tid >> 3) & 7;    // head
        const int pp = tid & 7;           // point pair (points 2pp, 2pp+1)
        const int l  = pp >> 1;           // level (pairs never straddle levels)

        const int W  = 176 >> l;
        const int Hh = 64  >> l;
        // level offsets 0, 11264, 14080, 14784 (geometric /4 partial sums)
        const int base = (45056 - (45056 >> (2 * l))) / 3;

        const unsigned loc4 = ((unsigned)(b * NQ + q0 + qi) * NHEADS + h) * 8 + pp;
        const float4 s = __ldg(reinterpret_cast<const float4*>(loc) + loc4);

        // Replicate reference arithmetic exactly (no fma contraction):
        // g = 2*s - 1 ; x = ((g + 1) * w) * 0.5 - 0.5 ; ix = rint(x)
        const float fW = (float)W, fH = (float)Hh;

        float gx0 = __fadd_rn(__fmul_rn(2.0f, s.x), -1.0f);
        float gy0 = __fadd_rn(__fmul_rn(2.0f, s.y), -1.0f);
        float x0  = __fadd_rn(__fmul_rn(__fmul_rn(__fadd_rn(gx0, 1.0f), fW), 0.5f), -0.5f);
        float y0  = __fadd_rn(__fmul_rn(__fmul_rn(__fadd_rn(gy0, 1.0f), fH), 0.5f), -0.5f);
        const int ix0 = __float2int_rn(x0);
        const int iy0 = __float2int_rn(y0);

        float gx1 = __fadd_rn(__fmul_rn(2.0f, s.z), -1.0f);
        float gy1 = __fadd_rn(__fmul_rn(2.0f, s.w), -1.0f);
        float x1  = __fadd_rn(__fmul_rn(__fmul_rn(__fadd_rn(gx1, 1.0f), fW), 0.5f), -0.5f);
        float y1  = __fadd_rn(__fmul_rn(__fmul_rn(__fadd_rn(gy1, 1.0f), fH), 0.5f), -0.5f);
        const int ix1 = __float2int_rn(x1);
        const int iy1 = __float2int_rn(y1);

        const bool v0 = ((unsigned)ix0 < (unsigned)W) & ((unsigned)iy0 < (unsigned)Hh);
        const bool v1 = ((unsigned)ix1 < (unsigned)W) & ((unsigned)iy1 < (unsigned)Hh);

        const int k0 = base + min(max(iy0, 0), Hh - 1) * W + min(max(ix0, 0), W - 1);
        const int k1 = base + min(max(iy1, 0), Hh - 1) * W + min(max(ix1, 0), W - 1);

        // One STS.128 writes both points (int2 slots 2pp, 2pp+1 of the row).
        reinterpret_cast<int4*>(skey)[(qi * NHEADS + h) * 9 + pp] =
            make_int4(k0 << 10, __float_as_int(v0 ? 1.0f : 0.0f),
                      k1 << 10, __float_as_int(v1 ? 1.0f : 0.0f));
    }

    __syncthreads();

    // ---------------- Phase 2: gather (warp = one query, 4 heads) ----------
    // Identical to the 205.7us R9 mainloop (16 independent LDS.64 + LDG.128).
    const int w     = tid >> 5;          // 0..7
    const int lane  = tid & 31;
    const int qi    = w >> 1;
    const int hbase = (w & 1) << 2;
    const int g     = lane >> 3;         // head group within warp
    const int h     = hbase + g;
    const int d4    = lane & 7;          // float4 slot within the 128B line

    const int q = q0 + qi;

    const char* vbase = reinterpret_cast<const char*>(value)
                      + (size_t)b * ((size_t)NKEYS * 1024) + (h << 7) + (d4 << 4);
    const int2* kp = &skey[(qi * NHEADS + h) * 18];

    float4 acc = make_float4(0.f, 0.f, 0.f, 0.f);
#pragma unroll
    for (int p = 0; p < 16; ++p) {
        const int2 km = kp[p];                                   // LDS.64, imm offset
        const float4 v = __ldg(reinterpret_cast<const float4*>(vbase + km.x));
        const float m = __int_as_float(km.y);
        acc.x = __fmaf_rn(v.x, m, acc.x);
        acc.y = __fmaf_rn(v.y, m, acc.y);
        acc.z = __fmaf_rn(v.z, m, acc.z);
        acc.w = __fmaf_rn(v.w, m, acc.w);
    }

    // Full-warp 512B store: 4 heads x 128B for this query.
    float4* op4 = reinterpret_cast<float4*>(out)
                + (((size_t)b * NQ + q) << 6) + (hbase << 3) + lane;
    *op4 = acc;
}

extern "C" void kernel_launch(void* const* d_in, const int* in_sizes, int n_in,
                              void* d_out, int out_size)
{
    const float* value = (const float*)d_in[0];
    // d_in[1] = value_spatial_shapes (constants, folded into the kernel)
    const float* loc   = (const float*)d_in[2];
    float* out         = (float*)d_out;

    dim3 grid(NQ / QPB, BS);
    msda_kernel<<<grid, 256>>>(value, loc, out);
}